// round 10
// baseline (speedup 1.0000x reference)
#include <cuda_runtime.h>
#include <cuda_bf16.h>
#include <math.h>

#define BB 4
#define HH 512
#define WW 512
#define NPIX (BB*HH*WW)
#define TW 32
#define TH 8

#define TAUc   0.01f
#define RHOc   1.99f
#define SIGMAc 1.3888888888888888f   // 1/0.01/72

// u2: 4x bf16 (uint2: .x word=(x,y), .y word=(z,w)). r2/rbar: 2x bf16 (u32).
typedef uint2 U2raw;
__device__ __align__(16) float    g_x2  [NPIX];
__device__ __align__(16) unsigned g_r2  [NPIX];
__device__ __align__(16) U2raw    g_u2  [NPIX];
__device__ __align__(16) float    g_xbar[NPIX];
__device__ __align__(16) unsigned g_rbar[NPIX];

static __device__ __forceinline__ float4 u2unpack2(unsigned lo, unsigned hi) {
    float2 f0 = __bfloat1622float2(*reinterpret_cast<__nv_bfloat162*>(&lo));
    float2 f1 = __bfloat1622float2(*reinterpret_cast<__nv_bfloat162*>(&hi));
    return make_float4(f0.x, f0.y, f1.x, f1.y);
}
static __device__ __forceinline__ float4 u2unpack(U2raw r) {
    return u2unpack2(r.x, r.y);
}
static __device__ __forceinline__ U2raw u2pack(float a, float b, float c, float d) {
    __nv_bfloat162 p0 = __floats2bfloat162_rn(a, b);
    __nv_bfloat162 p1 = __floats2bfloat162_rn(c, d);
    U2raw r;
    r.x = *reinterpret_cast<unsigned*>(&p0);
    r.y = *reinterpret_cast<unsigned*>(&p1);
    return r;
}
static __device__ __forceinline__ float2 bf2unpack(unsigned r) {
    return __bfloat1622float2(*reinterpret_cast<__nv_bfloat162*>(&r));
}
static __device__ __forceinline__ unsigned bf2pack(float a, float b) {
    __nv_bfloat162 p = __floats2bfloat162_rn(a, b);
    return *reinterpret_cast<unsigned*>(&p);
}

// ---------------------------------------------------------------------------
// Kernel A, 2x2 pixel quads (coalescing-preserving, LSU-op minimized).
// Each thread handles (h..h+1, w..w+1), h,w even. 28 mem-ops/quad.
// Uses zero-padding + invariants u2.y==0 at w=0, u2.w==0 at h=H-1.
// ---------------------------------------------------------------------------
template<bool LAST>
__global__ void __launch_bounds__(256)
k_A(const float* __restrict__ y, const int* __restrict__ ths,
    float* __restrict__ outx) {
    const int w = (blockIdx.x * 32 + threadIdx.x) * 2;   // even, <= 510
    const int h = (blockIdx.y * 8 + threadIdx.y) * 2;    // even, <= 510
    const int b = blockIdx.z;
    const int i = (b * HH + h) * WW + w;
    const U2raw* u2b = g_u2 + (size_t)b * HH * WW;

    const bool hasL = (w > 0);
    const bool hasR = (w + 2 < WW);
    const bool hasU = (h > 0);
    const bool hasD = (h + 2 < HH);

    // rows h (r0) and h+1 (r1): center LDG.128, left word, right uint2
    const uint4 cc0 = __ldg((const uint4*)(u2b + h * WW + w));
    const uint4 cc1 = __ldg((const uint4*)(u2b + (h + 1) * WW + w));
    const float4 a00 = u2unpack2(cc0.x, cc0.y);   // (h,   w)
    const float4 a01 = u2unpack2(cc0.z, cc0.w);   // (h,   w+1)
    const float4 a10 = u2unpack2(cc1.x, cc1.y);   // (h+1, w)
    const float4 a11 = u2unpack2(cc1.z, cc1.w);   // (h+1, w+1)

    float2 l0 = make_float2(0.f, 0.f), l1 = l0;   // (x,y) at w-1
    if (hasL) {
        l0 = bf2unpack(__ldg(&(u2b + h * WW + w - 1)->x));
        l1 = bf2unpack(__ldg(&(u2b + (h + 1) * WW + w - 1)->x));
    }
    float r0y = 0.f, r0z = 0.f, r1y = 0.f, r1z = 0.f;  // at w+2
    if (hasR) {
        U2raw rr0 = __ldg(u2b + h * WW + w + 2);
        U2raw rr1 = __ldg(u2b + (h + 1) * WW + w + 2);
        float2 t;
        t = bf2unpack(rr0.x); r0y = t.y;
        t = bf2unpack(rr0.y); r0z = t.x;
        t = bf2unpack(rr1.x); r1y = t.y;
        t = bf2unpack(rr1.y); r1z = t.x;
    }
    // row h-1: (z,w) at w, w+1; z at w+2
    float2 u0 = make_float2(0.f, 0.f), u1 = u0;
    float urz = 0.f;
    if (hasU) {
        const U2raw* up = u2b + (h - 1) * WW + w;
        u0 = bf2unpack(__ldg(&up->y));
        u1 = bf2unpack(__ldg(&(up + 1)->y));
        if (hasR) urz = bf2unpack(__ldg(&(up + 2)->y)).x;
    }
    // row h-2: w component at w, w+1
    float w20 = 0.f, w21 = 0.f;
    if (h >= 2) {
        const U2raw* p2 = u2b + (h - 2) * WW + w;
        w20 = bf2unpack(__ldg(&p2->y)).y;
        w21 = bf2unpack(__ldg(&(p2 + 1)->y)).y;
    }
    // row h+2: x component at w-1, w, w+1
    float d0 = 0.f, d1 = 0.f, dl = 0.f;
    if (hasD) {
        const U2raw* pd = u2b + (h + 2) * WW + w;
        d0 = bf2unpack(__ldg(&pd->x)).x;
        d1 = bf2unpack(__ldg(&(pd + 1)->x)).x;
        if (hasL) dl = bf2unpack(__ldg(&(pd - 1)->x)).x;
    }

    // tmp values (unconditional forms rely on zero-pad + invariants)
    const float t0p00 = TAUc * (a00.x - a10.x - a01.y + a00.y);
    const float t0p01 = TAUc * (a01.x - a11.x - r0y   + a01.y);
    const float t0l0  = TAUc * (l0.x  - l1.x  - a00.y + l0.y);
    const float t1p00 = TAUc * (a00.z - a01.z - a00.w + u0.y);
    const float t1p01 = TAUc * (a01.z - r0z   - a01.w + u1.y);
    const float t1u00 = TAUc * (u0.x  - u1.x  - u0.y  + w20);
    const float t1u01 = TAUc * (u1.x  - urz   - u1.y  + w21);

    const float t0p10 = TAUc * (a10.x - d0    - a11.y + a10.y);
    const float t0p11 = TAUc * (a11.x - d1    - r1y   + a11.y);
    const float t0l1  = TAUc * (l1.x  - dl    - a10.y + l1.y);
    const float t1p10 = TAUc * (a10.z - a11.z - a10.w + a00.w);
    const float t1p11 = TAUc * (a11.z - r1z   - a11.w + a01.w);

    // divergences (h even <=510: h<511 always; h+1>0 always; w<511 always; w+1>0 always)
    float dv00 = -t1p00 - t0p00;
    if (hasL) dv00 += t0l0;
    if (hasU) dv00 += t1u00;

    float dv01 = -t1p01 + t0p00;
    if (hasR) dv01 -= t0p01;      // w+1 < 511 iff w+2 < 512
    if (hasU) dv01 += t1u01;

    float dv10 = -t0p10 + t1p00;
    if (hasL) dv10 += t0l1;
    if (hasD) dv10 -= t1p10;

    float dv11 = t0p10 + t1p01;
    if (hasR) dv11 -= t0p11;
    if (hasD) dv11 -= t1p11;

    const float inv = 1.f / (1.f + TAUc);
    const float2 x2o0 = __ldg((const float2*)&g_x2[i]);
    const float2 x2o1 = __ldg((const float2*)&g_x2[i + WW]);
    const float2 y0v  = __ldg((const float2*)&y[i]);
    const float2 y1v  = __ldg((const float2*)&y[i + WW]);

    const float x00 = (x2o0.x - dv00 + TAUc * y0v.x) * inv;
    const float x01 = (x2o0.y - dv01 + TAUc * y0v.y) * inv;
    const float x10 = (x2o1.x - dv10 + TAUc * y1v.x) * inv;
    const float x11 = (x2o1.y - dv11 + TAUc * y1v.y) * inv;

    const float n00 = x2o0.x + RHOc * (x00 - x2o0.x);
    const float n01 = x2o0.y + RHOc * (x01 - x2o0.y);
    const float n10 = x2o1.x + RHOc * (x10 - x2o1.x);
    const float n11 = x2o1.y + RHOc * (x11 - x2o1.y);

    if (LAST) {
        *(float2*)&outx[i]      = make_float2(n00, n01);
        *(float2*)&outx[i + WW] = make_float2(n10, n11);
        return;
    }

    *(float2*)&g_xbar[i]      = make_float2(2.f * x00 - x2o0.x, 2.f * x01 - x2o0.y);
    *(float2*)&g_xbar[i + WW] = make_float2(2.f * x10 - x2o1.x, 2.f * x11 - x2o1.y);
    *(float2*)&g_x2[i]        = make_float2(n00, n01);
    *(float2*)&g_x2[i + WW]   = make_float2(n10, n11);

    const float lam1 = 0.1f * (float)__ldg(ths);
    const float itl = 1.f / (TAUc * lam1);
    const uint2 r2a = __ldg((const uint2*)&g_r2[i]);
    const uint2 r2b = __ldg((const uint2*)&g_r2[i + WW]);

    uint2 rbarA, rbarB, r2nA, r2nB;
    {
        const float2 o = bf2unpack(r2a.x);
        const float rvx = o.x + t0p00, rvy = o.y + t1p00;
        const float s = 1.f - 1.f / fmaxf(sqrtf(rvx*rvx + rvy*rvy) * itl, 1.f);
        const float rx = rvx * s, ry = rvy * s;
        rbarA.x = bf2pack(2.f*rx - o.x, 2.f*ry - o.y);
        r2nA.x  = bf2pack(o.x + RHOc*(rx - o.x), o.y + RHOc*(ry - o.y));
    }
    {
        const float2 o = bf2unpack(r2a.y);
        const float rvx = o.x + t0p01, rvy = o.y + t1p01;
        const float s = 1.f - 1.f / fmaxf(sqrtf(rvx*rvx + rvy*rvy) * itl, 1.f);
        const float rx = rvx * s, ry = rvy * s;
        rbarA.y = bf2pack(2.f*rx - o.x, 2.f*ry - o.y);
        r2nA.y  = bf2pack(o.x + RHOc*(rx - o.x), o.y + RHOc*(ry - o.y));
    }
    {
        const float2 o = bf2unpack(r2b.x);
        const float rvx = o.x + t0p10, rvy = o.y + t1p10;
        const float s = 1.f - 1.f / fmaxf(sqrtf(rvx*rvx + rvy*rvy) * itl, 1.f);
        const float rx = rvx * s, ry = rvy * s;
        rbarB.x = bf2pack(2.f*rx - o.x, 2.f*ry - o.y);
        r2nB.x  = bf2pack(o.x + RHOc*(rx - o.x), o.y + RHOc*(ry - o.y));
    }
    {
        const float2 o = bf2unpack(r2b.y);
        const float rvx = o.x + t0p11, rvy = o.y + t1p11;
        const float s = 1.f - 1.f / fmaxf(sqrtf(rvx*rvx + rvy*rvy) * itl, 1.f);
        const float rx = rvx * s, ry = rvy * s;
        rbarB.y = bf2pack(2.f*rx - o.x, 2.f*ry - o.y);
        r2nB.y  = bf2pack(o.x + RHOc*(rx - o.x), o.y + RHOc*(ry - o.y));
    }
    *(uint2*)&g_rbar[i]      = rbarA;
    *(uint2*)&g_rbar[i + WW] = rbarB;
    *(uint2*)&g_r2[i]        = r2nA;
    *(uint2*)&g_r2[i + WW]   = r2nB;
}

// ---------------------------------------------------------------------------
// Kernel B (unchanged): v = nabla2(xbar) - rbar in shared, then
// u = prox_sigma_g_conj(u2 + SIGMA*eps2(v)) + relaxation (u2/rbar bf16).
// FIRST iteration: xbar == y, rbar == 0, u2 == 0; also initializes x2=y, r2=0.
// ---------------------------------------------------------------------------
template<bool FIRST>
__global__ void __launch_bounds__(TW*TH)
k_B(const float* __restrict__ y, const int* __restrict__ ths) {
    __shared__ float  sx[TH + 3][TW + 3];
    __shared__ float2 sv[TH + 2][TW + 2];

    const int tx = threadIdx.x, ty = threadIdx.y;
    const int tid = ty * TW + tx;
    const int w0 = blockIdx.x * TW, h0 = blockIdx.y * TH, b = blockIdx.z;
    const size_t boff = (size_t)b * HH * WW;
    const float* xb = FIRST ? (y + boff) : (g_xbar + boff);

    #pragma unroll
    for (int idx = tid; idx < (TH + 3) * (TW + 2); idx += TW * TH) {
        int rr = idx / (TW + 2), cc = idx % (TW + 2);
        int gh = h0 + rr - 1, gw = w0 + cc - 1;
        float v = 0.f;
        if (gh >= 0 && gh < HH && gw >= 0 && gw < WW) v = __ldg(xb + gh * WW + gw);
        sx[rr][cc] = v;
    }
    __syncthreads();

    #pragma unroll
    for (int idx = tid; idx < (TH + 2) * (TW + 1); idx += TW * TH) {
        int R = idx / (TW + 1), C = idx % (TW + 1);
        int gh = h0 + R - 1, gw = w0 + C - 1;
        float2 v = make_float2(0.f, 0.f);
        if (gh >= 0 && gh < HH && gw >= 0 && gw < WW) {
            float xc = sx[R][C];
            float v0 = (gw < WW - 1) ? (sx[R][C + 1] - xc) : 0.f;
            float v1 = (gh < HH - 1) ? (sx[R + 1][C] - xc) : 0.f;
            if (!FIRST) {
                float2 rb = bf2unpack(__ldg(&g_rbar[boff + gh * WW + gw]));
                v0 -= rb.x; v1 -= rb.y;
            }
            v = make_float2(v0, v1);
        }
        sv[R][C] = v;
    }
    __syncthreads();

    const int h = h0 + ty, w = w0 + tx;
    const int i = (int)boff + h * WW + w;

    float2 vc = sv[ty + 1][tx + 1];
    float2 vu = sv[ty][tx + 1];
    float2 vl = sv[ty + 1][tx];
    float2 vd = sv[ty + 2][tx + 1];

    float G0 = vc.x - vu.x;
    float G1 = (w > 0) ? (vc.x - vl.x) : 0.f;
    float G2 = vc.y - vl.y;
    float G3 = (h < HH - 1) ? (vd.y - vc.y) : 0.f;

    float4 u2o = FIRST ? make_float4(0.f, 0.f, 0.f, 0.f)
                       : u2unpack(__ldg(&g_u2[i]));
    float u0 = u2o.x + SIGMAc * G0;
    float u1 = u2o.y + SIGMAc * G1;
    float u2c = u2o.z + SIGMAc * G2;
    float u3 = u2o.w + SIGMAc * G3;

    float lam2 = 0.15f * (float)__ldg(ths);
    float nrm = sqrtf(u0 * u0 + u1 * u1 + u2c * u2c + u3 * u3);
    float sc = 1.f / fmaxf(nrm * (1.f / lam2), 1.f);
    u0 *= sc; u1 *= sc; u2c *= sc; u3 *= sc;

    g_u2[i] = u2pack(u2o.x + RHOc * (u0  - u2o.x),
                     u2o.y + RHOc * (u1  - u2o.y),
                     u2o.z + RHOc * (u2c - u2o.z),
                     u2o.w + RHOc * (u3  - u2o.w));

    if (FIRST) {
        g_x2[i] = sx[ty + 1][tx + 1];
        g_r2[i] = 0u;
    }
}

extern "C" void kernel_launch(void* const* d_in, const int* in_sizes, int n_in,
                              void* d_out, int out_size) {
    const float* y   = (const float*)d_in[0];
    const int*   ths = (const int*)d_in[1];
    float*       out = (float*)d_out;

    dim3 blkA(32, 8, 1);
    dim3 grdA(WW / 64, HH / 16, BB);     // 2x2 quad per thread
    dim3 blkB(TW, TH, 1);
    dim3 grdB(WW / TW, HH / TH, BB);

    // Iteration 1 (specialized: A is a no-op closed form)
    k_B<true><<<grdB, blkB>>>(y, ths);

    // Iterations 2..9
    for (int it = 1; it < 9; ++it) {
        k_A<false><<<grdA, blkA>>>(y, ths, nullptr);
        k_B<false><<<grdB, blkB>>>(y, ths);
    }

    // Iteration 10: only the x path matters; write straight to output.
    k_A<true><<<grdA, blkA>>>(y, ths, out);
}

// round 11
// speedup vs baseline: 1.0279x; 1.0279x over previous
#include <cuda_runtime.h>
#include <cuda_bf16.h>
#include <math.h>

#define BB 4
#define HH 512
#define WW 512
#define NPIX (BB*HH*WW)
#define TW 32
#define TH 8
#define FTW 64
#define FTH 16

#define TAUc   0.01f
#define RHOc   1.99f
#define SIGMAc 1.3888888888888888f   // 1/0.01/72

// Double-buffered state. u2: 4x bf16 (uint2). r2: 2x bf16 (u32). x2: fp32.
typedef uint2 U2raw;
__device__ __align__(16) float    g_x2a[NPIX], g_x2b[NPIX];
__device__ __align__(16) unsigned g_r2a[NPIX], g_r2b[NPIX];
__device__ __align__(16) U2raw    g_u2a[NPIX], g_u2b[NPIX];

static __device__ __forceinline__ float2 bf2unpack(unsigned r) {
    return __bfloat1622float2(*reinterpret_cast<__nv_bfloat162*>(&r));
}
static __device__ __forceinline__ unsigned bf2pack(float a, float b) {
    __nv_bfloat162 p = __floats2bfloat162_rn(a, b);
    return *reinterpret_cast<unsigned*>(&p);
}
static __device__ __forceinline__ U2raw u2pack(float a, float b, float c, float d) {
    U2raw r; r.x = bf2pack(a, b); r.y = bf2pack(c, d); return r;
}

// ---------------------------------------------------------------------------
// Fused iteration kernel: tmp -> x/xbar + r/rbar -> v -> u, all in smem on a
// 64x16 tile with halo recompute. Reads state IN buffers, writes OUT buffers
// (ping-pong, so halo reads never race tile writes).
// Frames (row offset, col offset vs tile origin):
//   su  22x68  (-3, -2)   u2 in
//   st  20x67  (-2, -2)   tmp
//   sxb 19x66  (-1, -1)   xbar ; srb same frame: rbar
//   sv  18x65  (-1, -1)   v
// Zero-padding + invariants (u2.y==0 at w=0, u2.w==0 at h=H-1) make the tmp
// formulas unconditional.
// ---------------------------------------------------------------------------
template<int P>   // P=0: a->b, P=1: b->a
__global__ void __launch_bounds__(256)
k_F(const float* __restrict__ y, const int* __restrict__ ths) {
    const float*    x2i = P ? g_x2b : g_x2a;
    float*          x2o = P ? g_x2a : g_x2b;
    const unsigned* r2i = P ? g_r2b : g_r2a;
    unsigned*       r2o = P ? g_r2a : g_r2b;
    const U2raw*    u2i = P ? g_u2b : g_u2a;
    U2raw*          u2o = P ? g_u2a : g_u2b;

    __shared__ uint2  su[22][68];
    __shared__ float2 st[20][67];
    __shared__ float  sxb[19][66];
    __shared__ float2 srb[19][66];
    __shared__ float2 sv[18][65];

    const int tid = threadIdx.y * 32 + threadIdx.x;
    const int w0 = blockIdx.x * FTW, h0 = blockIdx.y * FTH, b = blockIdx.z;
    const int boff = b * HH * WW;

    // Stage 1: load u2 tile with halo (zero-padded)
    for (int idx = tid; idx < 22 * 68; idx += 256) {
        int R = idx / 68, C = idx % 68;
        int gh = h0 + R - 3, gw = w0 + C - 2;
        uint2 v = make_uint2(0u, 0u);
        if ((unsigned)gh < HH && (unsigned)gw < WW)
            v = __ldg(&u2i[boff + gh * WW + gw]);
        su[R][C] = v;
    }
    __syncthreads();

    // Stage 2: tmp = TAU * eps2_adjoint(u2) on 20x67
    for (int idx = tid; idx < 20 * 67; idx += 256) {
        int R = idx / 67, C = idx % 67;              // su: [R+1][C]
        uint2 cw = su[R + 1][C];
        float2 cxy = bf2unpack(cw.x), czw = bf2unpack(cw.y);
        float  dnx = bf2unpack(su[R + 2][C].x).x;    // u2.x(h+1,w)
        uint2 rw = su[R + 1][C + 1];
        float2 rxy = bf2unpack(rw.x), rzw = bf2unpack(rw.y);
        float  upw = bf2unpack(su[R][C].y).y;        // u2.w(h-1,w)
        st[R][C] = make_float2(TAUc * (cxy.x - dnx   - rxy.y + cxy.y),
                               TAUc * (czw.x - rzw.x - czw.y + upw));
    }
    __syncthreads();

    // Stage 3: x/xbar + r/rbar on 19x66; write x2'/r2' for in-tile pixels
    const float lam1 = 0.1f * (float)__ldg(ths);
    const float itl  = 1.f / (TAUc * lam1);
    const float inv  = 1.f / (1.f + TAUc);
    for (int idx = tid; idx < 19 * 66; idx += 256) {
        int R = idx / 66, C = idx % 66;              // gh=h0+R-1, gw=w0+C-1
        int gh = h0 + R - 1, gw = w0 + C - 1;
        float xbv = 0.f;
        float2 rbv = make_float2(0.f, 0.f);
        if ((unsigned)gh < HH && (unsigned)gw < WW) {
            float2 tc = st[R + 1][C + 1];            // st: [R+1][C+1]
            float  tlx = st[R + 1][C].x;
            float  tuy = st[R][C + 1].y;
            float div = 0.f;
            if (gw < WW - 1) div -= tc.x;
            if (gw > 0)      div += tlx;
            if (gh < HH - 1) div -= tc.y;
            if (gh > 0)      div += tuy;
            int gi = boff + gh * WW + gw;
            float x2v = __ldg(&x2i[gi]);
            float x = (x2v - div + TAUc * __ldg(&y[gi])) * inv;
            xbv = 2.f * x - x2v;
            float2 r2v = bf2unpack(__ldg(&r2i[gi]));
            float rvx = r2v.x + tc.x, rvy = r2v.y + tc.y;
            float s = 1.f - 1.f / fmaxf(sqrtf(rvx*rvx + rvy*rvy) * itl, 1.f);
            float rx = rvx * s, ry = rvy * s;
            rbv = make_float2(2.f * rx - r2v.x, 2.f * ry - r2v.y);
            if ((unsigned)(gh - h0) < FTH && (unsigned)(gw - w0) < FTW) {
                x2o[gi] = x2v + RHOc * (x - x2v);
                r2o[gi] = bf2pack(r2v.x + RHOc * (rx - r2v.x),
                                  r2v.y + RHOc * (ry - r2v.y));
            }
        }
        sxb[R][C] = xbv;
        srb[R][C] = rbv;
    }
    __syncthreads();

    // Stage 4: v = nabla2(xbar) - rbar on 18x65 (zero outside image)
    for (int idx = tid; idx < 18 * 65; idx += 256) {
        int R = idx / 65, C = idx % 65;              // gh=h0+R-1, gw=w0+C-1
        int gh = h0 + R - 1, gw = w0 + C - 1;
        float2 v = make_float2(0.f, 0.f);
        if ((unsigned)gh < HH && (unsigned)gw < WW) {
            float xc = sxb[R][C];
            float2 rb = srb[R][C];
            float v0 = ((gw < WW - 1) ? (sxb[R][C + 1] - xc) : 0.f) - rb.x;
            float v1 = ((gh < HH - 1) ? (sxb[R + 1][C] - xc) : 0.f) - rb.y;
            v = make_float2(v0, v1);
        }
        sv[R][C] = v;
    }
    __syncthreads();

    // Stage 5: u-prox + relaxation on the 64x16 tile
    const float lam2 = 0.15f * (float)__ldg(ths);
    const float il2 = 1.f / lam2;
    for (int idx = tid; idx < FTH * FTW; idx += 256) {
        int R = idx / FTW, C = idx % FTW;            // gh=h0+R, gw=w0+C
        int gh = h0 + R, gw = w0 + C;
        float2 vc = sv[R + 1][C + 1];
        float2 vu = sv[R][C + 1];
        float2 vl = sv[R + 1][C];
        float2 vd = sv[R + 2][C + 1];

        float G0 = vc.x - vu.x;
        float G1 = (gw > 0) ? (vc.x - vl.x) : 0.f;
        float G2 = vc.y - vl.y;
        float G3 = (gh < HH - 1) ? (vd.y - vc.y) : 0.f;

        uint2 uo = su[R + 3][C + 2];
        float2 o0 = bf2unpack(uo.x), o1 = bf2unpack(uo.y);
        float u0 = o0.x + SIGMAc * G0;
        float u1 = o0.y + SIGMAc * G1;
        float u2c = o1.x + SIGMAc * G2;
        float u3 = o1.y + SIGMAc * G3;
        float nrm = sqrtf(u0*u0 + u1*u1 + u2c*u2c + u3*u3);
        float sc = 1.f / fmaxf(nrm * il2, 1.f);
        u2o[boff + gh * WW + gw] =
            u2pack(o0.x + RHOc * (u0  * sc - o0.x),
                   o0.y + RHOc * (u1  * sc - o0.y),
                   o1.x + RHOc * (u2c * sc - o1.x),
                   o1.y + RHOc * (u3  * sc - o1.y));
    }
}

// ---------------------------------------------------------------------------
// Iteration 1 (closed form: x=xbar=y, r=rbar=0, u2=0): u-update from y only;
// initializes x2=y, r2=0, u2 into buffer A.
// ---------------------------------------------------------------------------
__global__ void __launch_bounds__(TW*TH)
k_B_first(const float* __restrict__ y, const int* __restrict__ ths) {
    __shared__ float  sx[TH + 3][TW + 3];
    __shared__ float2 svv[TH + 2][TW + 2];

    const int tx = threadIdx.x, ty = threadIdx.y;
    const int tid = ty * TW + tx;
    const int w0 = blockIdx.x * TW, h0 = blockIdx.y * TH, b = blockIdx.z;
    const int boff = b * HH * WW;
    const float* xb = y + boff;

    #pragma unroll
    for (int idx = tid; idx < (TH + 3) * (TW + 2); idx += TW * TH) {
        int rr = idx / (TW + 2), cc = idx % (TW + 2);
        int gh = h0 + rr - 1, gw = w0 + cc - 1;
        float v = 0.f;
        if (gh >= 0 && gh < HH && gw >= 0 && gw < WW) v = __ldg(xb + gh * WW + gw);
        sx[rr][cc] = v;
    }
    __syncthreads();

    #pragma unroll
    for (int idx = tid; idx < (TH + 2) * (TW + 1); idx += TW * TH) {
        int R = idx / (TW + 1), C = idx % (TW + 1);
        int gh = h0 + R - 1, gw = w0 + C - 1;
        float2 v = make_float2(0.f, 0.f);
        if (gh >= 0 && gh < HH && gw >= 0 && gw < WW) {
            float xc = sx[R][C];
            float v0 = (gw < WW - 1) ? (sx[R][C + 1] - xc) : 0.f;
            float v1 = (gh < HH - 1) ? (sx[R + 1][C] - xc) : 0.f;
            v = make_float2(v0, v1);
        }
        svv[R][C] = v;
    }
    __syncthreads();

    const int h = h0 + ty, w = w0 + tx;
    const int i = boff + h * WW + w;

    float2 vc = svv[ty + 1][tx + 1];
    float2 vu = svv[ty][tx + 1];
    float2 vl = svv[ty + 1][tx];
    float2 vd = svv[ty + 2][tx + 1];

    float G0 = vc.x - vu.x;
    float G1 = (w > 0) ? (vc.x - vl.x) : 0.f;
    float G2 = vc.y - vl.y;
    float G3 = (h < HH - 1) ? (vd.y - vc.y) : 0.f;

    float u0 = SIGMAc * G0, u1 = SIGMAc * G1;
    float u2c = SIGMAc * G2, u3 = SIGMAc * G3;
    float lam2 = 0.15f * (float)__ldg(ths);
    float nrm = sqrtf(u0*u0 + u1*u1 + u2c*u2c + u3*u3);
    float sc = RHOc / fmaxf(nrm * (1.f / lam2), 1.f);
    g_u2a[i] = u2pack(u0 * sc, u1 * sc, u2c * sc, u3 * sc);
    g_x2a[i] = sx[ty + 1][tx + 1];
    g_r2a[i] = 0u;
}

// ---------------------------------------------------------------------------
// Iteration 10 (x path only, 2-row coarsened; reads buffer A, writes out).
// ---------------------------------------------------------------------------
__global__ void __launch_bounds__(256)
k_A_last(const float* __restrict__ y, float* __restrict__ outx) {
    const int w = blockIdx.x * 32 + threadIdx.x;
    const int h = (blockIdx.y * 8 + threadIdx.y) * 2;
    const int b = blockIdx.z;
    const int i = (b * HH + h) * WW + w;
    const U2raw* p0 = g_u2a + b * HH * WW + h * WW + w;

    const uint2 w0c = __ldg(p0);
    const uint2 w1c = __ldg(p0 + WW);
    float2 c0xy = bf2unpack(w0c.x), c0zw = bf2unpack(w0c.y);
    float2 c1xy = bf2unpack(w1c.x), c1zw = bf2unpack(w1c.y);
    float2 r0xy = make_float2(0,0), r0zw = r0xy, r1xy = r0xy, r1zw = r0xy;
    if (w < WW - 1) {
        uint2 a = __ldg(p0 + 1), bb2 = __ldg(p0 + WW + 1);
        r0xy = bf2unpack(a.x); r0zw = bf2unpack(a.y);
        r1xy = bf2unpack(bb2.x); r1zw = bf2unpack(bb2.y);
    }
    float2 upzw = make_float2(0,0);
    if (h > 0) upzw = bf2unpack(__ldg(&(p0 - WW)->y));
    float2 l0 = make_float2(0,0), l1 = l0;
    if (w > 0) {
        l0 = bf2unpack(__ldg(&(p0 - 1)->x));
        l1 = bf2unpack(__ldg(&(p0 + WW - 1)->x));
    }
    float Xd1 = 0.f, Xdl1 = 0.f;
    if (h + 2 < HH) {
        Xd1 = bf2unpack(__ldg(&(p0 + 2 * WW)->x)).x;
        if (w > 0) Xdl1 = bf2unpack(__ldg(&(p0 + 2 * WW - 1)->x)).x;
    }
    float Zur0 = 0.f;
    if (h > 0 && w < WW - 1) Zur0 = bf2unpack(__ldg(&(p0 - WW + 1)->y)).x;
    float Wu20 = 0.f;
    if (h >= 2) Wu20 = bf2unpack(__ldg(&(p0 - 2 * WW)->y)).y;

    const float t0p0 = TAUc * (c0xy.x - c1xy.x - r0xy.y + c0xy.y);
    const float t1p0 = TAUc * (c0zw.x - r0zw.x - c0zw.y + upzw.y);
    const float t0l0 = TAUc * (l0.x - l1.x - c0xy.y + l0.y);
    const float t1u0 = TAUc * (upzw.x - Zur0 - upzw.y + Wu20);
    const float t0p1 = TAUc * (c1xy.x - Xd1 - r1xy.y + c1xy.y);
    const float t1p1 = TAUc * (c1zw.x - r1zw.x - c1zw.y + c0zw.y);
    const float t0l1 = TAUc * (l1.x - Xdl1 - c1xy.y + l1.y);

    float dv0 = -t1p0;
    if (w < WW - 1) dv0 -= t0p0;
    if (w > 0)      dv0 += t0l0;
    if (h > 0)      dv0 += t1u0;

    float dv1 = t1p0;
    if (w < WW - 1)  dv1 -= t0p1;
    if (w > 0)       dv1 += t0l1;
    if (h + 2 < HH)  dv1 -= t1p1;

    const float inv = 1.f / (1.f + TAUc);
    const float x2o0 = __ldg(&g_x2a[i]);
    const float x2o1 = __ldg(&g_x2a[i + WW]);
    const float x0 = (x2o0 - dv0 + TAUc * __ldg(&y[i])) * inv;
    const float x1 = (x2o1 - dv1 + TAUc * __ldg(&y[i + WW])) * inv;
    outx[i]      = x2o0 + RHOc * (x0 - x2o0);
    outx[i + WW] = x2o1 + RHOc * (x1 - x2o1);
}

extern "C" void kernel_launch(void* const* d_in, const int* in_sizes, int n_in,
                              void* d_out, int out_size) {
    const float* y   = (const float*)d_in[0];
    const int*   ths = (const int*)d_in[1];
    float*       out = (float*)d_out;

    dim3 blkB(TW, TH, 1);
    dim3 grdB(WW / TW, HH / TH, BB);
    dim3 blkF(32, 8, 1);
    dim3 grdF(WW / FTW, HH / FTH, BB);
    dim3 blkL(32, 8, 1);
    dim3 grdL(WW / 32, HH / 16, BB);

    // Iteration 1 (closed form) -> buffer A
    k_B_first<<<grdB, blkB>>>(y, ths);

    // Iterations 2..9: fused, ping-pong A<->B (ends in A after 8)
    for (int it = 0; it < 4; ++it) {
        k_F<0><<<grdF, blkF>>>(y, ths);   // A -> B
        k_F<1><<<grdF, blkF>>>(y, ths);   // B -> A
    }

    // Iteration 10: x path only, straight to output (reads A)
    k_A_last<<<grdL, blkL>>>(y, out);
}